// round 13
// baseline (speedup 1.0000x reference)
#include <cuda_runtime.h>
#include <cuda_fp16.h>
#include <cstdint>
#include <cstddef>

// ---------------- problem constants ----------------
#define B_    32
#define NTOK  3136
#define C_    512
#define NH    8
#define S_    49
#define G_    64
#define M_    (B_*G_*S_)    // 100352 (784*128)
#define QKVN  1536
#define SCALE_ 0.125f
#define L2T_OVER16 0.8304820237218406f

// ---------------- scratch ----------------
__device__ __half g_qkv[(size_t)M_ * QKVN];      // fp16 qkv (roped), (b,g,s) rows
__device__ __half g_xh[(size_t)M_ * C_];         // gathered x, fp16
__device__ __half g_wh[QKVN * C_];               // w_qkv, fp16
__device__ __half g_ph[C_ * C_];                 // w_proj, fp16
__device__ __half g_ah[(size_t)M_ * C_];         // attention out, fp16, (b,n) rows

// row r (in b,g,s order) -> x row offset (b,n)
__device__ __forceinline__ size_t gather_row_off(int r) {
    int b   = r / (G_ * S_);
    int rem = r - b * (G_ * S_);
    int g   = rem / S_;
    int s   = rem - g * S_;
    int sy  = s / 7;
    int sx  = s - sy * 7;
    int n   = ((g >> 3) * 7 + sy) * 56 + (g & 7) * 7 + sx;
    return ((size_t)b * NTOK + n) * C_;
}

// ---------------- asm wrappers ----------------
__device__ __forceinline__ uint32_t smem_u32(const void* p) {
    uint32_t a;
    asm("{ .reg .u64 t; cvta.to.shared.u64 t, %1; cvt.u32.u64 %0, t; }" : "=r"(a) : "l"(p));
    return a;
}
__device__ __forceinline__ void cp16(uint32_t saddr, const void* g) {
    asm volatile("cp.async.cg.shared.global [%0], [%1], 16;" :: "r"(saddr), "l"(g));
}
__device__ __forceinline__ void cp_commit() {
    asm volatile("cp.async.commit_group;" ::: "memory");
}
__device__ __forceinline__ void cp_wait0() {
    asm volatile("cp.async.wait_group 0;" ::: "memory");
}
__device__ __forceinline__ void cp_wait1() {
    asm volatile("cp.async.wait_group 1;" ::: "memory");
}
__device__ __forceinline__ void cp_wait2() {
    asm volatile("cp.async.wait_group 2;" ::: "memory");
}
__device__ __forceinline__ void ldm4(uint32_t* r, uint32_t addr) {
    asm volatile("ldmatrix.sync.aligned.m8n8.x4.shared.b16 {%0,%1,%2,%3}, [%4];"
        : "=r"(r[0]), "=r"(r[1]), "=r"(r[2]), "=r"(r[3]) : "r"(addr));
}
__device__ __forceinline__ void ldm4t(uint32_t* r, uint32_t addr) {
    asm volatile("ldmatrix.sync.aligned.m8n8.x4.trans.shared.b16 {%0,%1,%2,%3}, [%4];"
        : "=r"(r[0]), "=r"(r[1]), "=r"(r[2]), "=r"(r[3]) : "r"(addr));
}
__device__ __forceinline__ void mma16816(float* c, const uint32_t* a, const uint32_t* b) {
    asm volatile("mma.sync.aligned.m16n8k16.row.col.f32.f16.f16.f32 "
        "{%0,%1,%2,%3}, {%4,%5,%6,%7}, {%8,%9}, {%0,%1,%2,%3};"
        : "+f"(c[0]), "+f"(c[1]), "+f"(c[2]), "+f"(c[3])
        : "r"(a[0]), "r"(a[1]), "r"(a[2]), "r"(a[3]), "r"(b[0]), "r"(b[1]));
}

// ---------------- conversion kernels ----------------
__global__ __launch_bounds__(256) void conv_x_kernel(const float* __restrict__ x) {
    int idx = blockIdx.x * 256 + threadIdx.x;       // M_*128 threads
    int r = idx >> 7;
    int q = (idx & 127) << 2;
    float4 v = *(const float4*)(x + gather_row_off(r) + q);
    __half2 a, b;
    a.x = __float2half_rn(v.x); a.y = __float2half_rn(v.y);
    b.x = __float2half_rn(v.z); b.y = __float2half_rn(v.w);
    size_t o = (size_t)r * C_ + q;
    *(uint2*)(g_xh + o) = make_uint2(*(uint32_t*)&a, *(uint32_t*)&b);
}

__global__ __launch_bounds__(256) void conv_w_kernel(const float* __restrict__ w,
                                                     __half* __restrict__ h) {
    int idx = blockIdx.x * 256 + threadIdx.x;
    size_t o = (size_t)idx << 2;
    float4 v = *(const float4*)(w + o);
    __half2 a, b;
    a.x = __float2half_rn(v.x); a.y = __float2half_rn(v.y);
    b.x = __float2half_rn(v.z); b.y = __float2half_rn(v.w);
    *(uint2*)(h + o) = make_uint2(*(uint32_t*)&a, *(uint32_t*)&b);
}

// ---------------- fp16 HMMA GEMM ----------------
// C[r][d] = sum_k A[r][k]*B[d][k] (+bias / +rope), K=512
// block 128x128, 8 warps (2x4), warp tile 64x32, BK=32, 4-stage cp.async
// Tiles row-paired: 2 logical rows (64B) per 128B physical row, xor swizzle.
// smem per stage: A(8K) pad(8K) B(8K)
#define STG_BYTES 24576u
#define NSTG 4
#define DYN_SMEM (NSTG * STG_BYTES)

// HALFOUT: write __half output (with fused RoPE); else fp32 (+bias)
template <int NCOLS, bool BIAS, bool ROPE, bool HALFOUT>
__global__ __launch_bounds__(256, 2) void mma_gemm(
    const __half* __restrict__ Am, const __half* __restrict__ Bm,
    const float* __restrict__ bias, void* __restrict__ Cout)
{
    extern __shared__ __align__(1024) char dyn[];
    const uint32_t sbase = smem_u32(dyn);

    const int tid  = threadIdx.x;
    const int lane = tid & 31;
    const int wid  = tid >> 5;
    const int wm   = wid >> 2;
    const int wn   = wid & 3;
    const int bm   = blockIdx.y * 128;
    const int bn   = blockIdx.x * 128;

    // ---- loader: all 256 threads, 4 cp16 each ----
    // tid>>7: 0=A, 1=B.  (tid>>6)&1 selects logical row within phys row.
    const int mat  = tid >> 7;
    const int half = (tid >> 6) & 1;
    const int prow = tid & 63;
    const __half* gsrc = (mat == 0) ? (Am + (size_t)bm * C_)
                                    : (Bm + (size_t)bn * C_);
    const __half* grow = gsrc + (size_t)(2 * prow + half) * C_;
    const uint32_t smat = sbase + (uint32_t)mat * 16384u + (uint32_t)prow * 128u;
    const int sx = prow & 7;

    auto load_stage = [&](int st, int kc) {
        const char* g0 = (const char*)(grow + kc * 32);
        uint32_t rb = smat + (uint32_t)st * STG_BYTES;
        #pragma unroll
        for (int c2 = 0; c2 < 4; c2++) {
            int c = half * 4 + c2;
            cp16(rb + (uint32_t)((c ^ sx) << 4), g0 + c2 * 16);
        }
    };

    // ---- fragment smem offsets (stage-relative), precomputed per ks ----
    const int a_r  = wm * 64 + (lane & 15);
    const int a_cp = lane >> 4;
    const int b_r0 = wn * 32 + (lane & 7) + ((lane & 16) >> 1);
    const int b_cp = (lane >> 3) & 1;

    uint32_t aoff[2][4], boff[2][2];
    #pragma unroll
    for (int ks = 0; ks < 2; ks++) {
        #pragma unroll
        for (int i = 0; i < 4; i++) {
            int r  = a_r + i * 16;
            int pr = r >> 1;
            int pc = ((r & 1) << 2) + 2 * ks + a_cp;
            aoff[ks][i] = (uint32_t)(pr * 128 + ((pc ^ (pr & 7)) << 4));
        }
        #pragma unroll
        for (int jj = 0; jj < 2; jj++) {
            int r  = b_r0 + jj * 16;
            int pr = r >> 1;
            int pc = ((r & 1) << 2) + 2 * ks + b_cp;
            boff[ks][jj] = 16384u + (uint32_t)(pr * 128 + ((pc ^ (pr & 7)) << 4));
        }
    }

    float acc[4][4][4];
    #pragma unroll
    for (int i = 0; i < 4; i++)
        #pragma unroll
        for (int j = 0; j < 4; j++)
            #pragma unroll
            for (int p = 0; p < 4; p++) acc[i][j][p] = 0.0f;

    load_stage(0, 0); cp_commit();
    load_stage(1, 1); cp_commit();
    load_stage(2, 2); cp_commit();

    uint32_t ah[2][4][4], bf[2][2][4];

    auto load_frags = [&](int buf, uint32_t base, int ks) {
        #pragma unroll
        for (int i = 0; i < 4; i++)
            ldm4(ah[buf][i], base + aoff[ks][i]);
        #pragma unroll
        for (int jj = 0; jj < 2; jj++)
            ldm4(bf[buf][jj], base + boff[ks][jj]);
    };
    auto do_mmas = [&](int buf) {
        #pragma unroll
        for (int i = 0; i < 4; i++)
            #pragma unroll
            for (int j = 0; j < 4; j++)
                mma16816(acc[i][j], ah[buf][i], &bf[buf][j >> 1][(j & 1) * 2]);
    };

    #pragma unroll 1
    for (int kc = 0; kc < 16; kc++) {
        if      (kc <= 13) cp_wait2();
        else if (kc == 14) cp_wait1();
        else               cp_wait0();
        __syncthreads();
        if (kc + 3 < 16) { load_stage((kc + 3) % NSTG, kc + 3); cp_commit(); }

        const uint32_t base = sbase + (uint32_t)(kc % NSTG) * STG_BYTES;
        load_frags(0, base, 0);
        load_frags(1, base, 1);
        do_mmas(0);
        do_mmas(1);
    }

    const int orow = bm + wm * 64 + (lane >> 2);
    const int ocol = bn + wn * 32 + (lane & 3) * 2;
    float bvx[4], bvy[4];
    if (BIAS) {
        #pragma unroll
        for (int j = 0; j < 4; j++) { bvx[j] = bias[ocol + j * 8]; bvy[j] = bias[ocol + j * 8 + 1]; }
    }
    #pragma unroll
    for (int i = 0; i < 4; i++) {
        const int rA = orow + i * 16;
        const int rB = rA + 8;
        int sA = 0, sB = 0;
        if (ROPE) { sA = rA % S_; sB = rB % S_; }
        #pragma unroll
        for (int j = 0; j < 4; j++) {
            const int cc = ocol + j * 8;
            float v0 = acc[i][j][0], v1 = acc[i][j][1];
            float v2 = acc[i][j][2], v3 = acc[i][j][3];
            if (ROPE && cc < 1024) {
                int m = (cc & 63) >> 1;
                float freq = exp2f(-(float)(m >> 1) * L2T_OVER16);
                float pA = (m & 1) ? (float)(sA / 7) : (float)(sA % 7);
                float pB = (m & 1) ? (float)(sB / 7) : (float)(sB % 7);
                float snA, csA, snB, csB;
                sincosf(pA * freq, &snA, &csA);
                sincosf(pB * freq, &snB, &csB);
                float t0 = v0 * csA - v1 * snA, t1 = v0 * snA + v1 * csA;
                float t2 = v2 * csB - v3 * snB, t3 = v2 * snB + v3 * csB;
                v0 = t0; v1 = t1; v2 = t2; v3 = t3;
            }
            if (BIAS) { v0 += bvx[j]; v1 += bvy[j]; v2 += bvx[j]; v3 += bvy[j]; }
            if (HALFOUT) {
                __half* Ch = (__half*)Cout;
                __half2 hA, hB;
                hA.x = __float2half_rn(v0); hA.y = __float2half_rn(v1);
                hB.x = __float2half_rn(v2); hB.y = __float2half_rn(v3);
                *(uint32_t*)(Ch + (size_t)rA * NCOLS + cc) = *(uint32_t*)&hA;
                *(uint32_t*)(Ch + (size_t)rB * NCOLS + cc) = *(uint32_t*)&hB;
            } else {
                float* Cf = (float*)Cout;
                *(float2*)(Cf + (size_t)rA * NCOLS + cc) = make_float2(v0, v1);
                *(float2*)(Cf + (size_t)rB * NCOLS + cc) = make_float2(v2, v3);
            }
        }
    }
}

// ---------------- tensor-core windowed attention (fp16 in, 2 heads/block) ----------------
// block = 256 threads; subgroup of 128 per head. S=49 padded to 64.
// per-head smem tiles (64 rows x 128B, xor swizzle): QH 0, KK 8192, VH 16384 (24KB/head)
#define T_QH 0u
#define T_KK 8192u
#define T_VH 16384u
#define HEAD_SM 24576

__global__ __launch_bounds__(256) void attn_tc_kernel() {
    __shared__ __align__(1024) char small[2 * HEAD_SM];

    const int tid0 = threadIdx.x;
    const int sub  = tid0 >> 7;           // which head of the pair
    const int tid  = tid0 & 127;
    const int lane = tid & 31;
    const int w    = tid >> 5;
    const int hp   = blockIdx.x & 3;      // head pair
    const int bg   = blockIdx.x >> 2;
    const int h    = hp * 2 + sub;
    char* sm = small + sub * HEAD_SM;
    const uint32_t sb = smem_u32(sm);
    const size_t base = (size_t)bg * S_ * QKVN + h * 64;

    // zero-fill both heads' tiles (padding rows must be 0)
    #pragma unroll
    for (int i = tid; i < HEAD_SM / 16; i += 128)
        ((uint4*)sm)[i] = make_uint4(0, 0, 0, 0);
    __syncthreads();

    // fill rows 0..48: straight swizzled 16B copies (already fp16)
    for (int i = tid; i < S_ * 8; i += 128) {
        int s   = i >> 3;
        int seg = i & 7;
        size_t ro = base + (size_t)s * QKVN + seg * 8;
        uint4 q = *(const uint4*)(g_qkv + ro);
        uint4 k = *(const uint4*)(g_qkv + ro + 512);
        uint4 v = *(const uint4*)(g_qkv + ro + 1024);
        uint32_t addr = (uint32_t)(s * 128 + ((seg ^ (s & 7)) << 4));
        *(uint4*)(sm + T_QH + addr) = q;
        *(uint4*)(sm + T_KK + addr) = k;
        *(uint4*)(sm + T_VH + addr) = v;
    }
    __syncthreads();

    // ---- QK^T: warp w -> score rows w*16..w*16+15, cols 0..63 ----
    const int a_r  = w * 16 + (lane & 15);
    const int a_cp = lane >> 4;
    const int b_r0 = (lane & 7) + ((lane & 16) >> 1);
    const int b_cp = (lane >> 3) & 1;

    float sc[8][4];
    #pragma unroll
    for (int j = 0; j < 8; j++)
        #pragma unroll
        for (int p = 0; p < 4; p++) sc[j][p] = 0.0f;

    #pragma unroll
    for (int ks = 0; ks < 4; ks++) {
        uint32_t aq[4], bk[4][4];
        {
            int ch = 2 * ks + a_cp;
            ldm4(aq, sb + T_QH + (uint32_t)(a_r * 128 + ((ch ^ (a_r & 7)) << 4)));
        }
        #pragma unroll
        for (int jn = 0; jn < 4; jn++) {
            int r  = jn * 16 + b_r0;
            int ch = 2 * ks + b_cp;
            ldm4(bk[jn], sb + T_KK + (uint32_t)(r * 128 + ((ch ^ (r & 7)) << 4)));
        }
        #pragma unroll
        for (int j = 0; j < 8; j++)
            mma16816(sc[j], aq, &bk[j >> 1][(j & 1) * 2]);
    }

    // ---- register softmax ----
    #pragma unroll
    for (int j = 0; j < 8; j++) {
        int t0 = j * 8 + 2 * (lane & 3);
        sc[j][0] = (t0     < S_) ? sc[j][0] * SCALE_ : -1e30f;
        sc[j][1] = (t0 + 1 < S_) ? sc[j][1] * SCALE_ : -1e30f;
        sc[j][2] = (t0     < S_) ? sc[j][2] * SCALE_ : -1e30f;
        sc[j][3] = (t0 + 1 < S_) ? sc[j][3] * SCALE_ : -1e30f;
    }
    float mx0 = -1e30f, mx1 = -1e30f;
    #pragma unroll
    for (int j = 0; j < 8; j++) {
        mx0 = fmaxf(mx0, fmaxf(sc[j][0], sc[j][1]));
        mx1 = fmaxf(mx1, fmaxf(sc[j][2], sc[j][3]));
    }
    mx0 = fmaxf(mx0, __shfl_xor_sync(0xffffffffu, mx0, 1));
    mx0 = fmaxf(mx0, __shfl_xor_sync(0xffffffffu, mx0, 2));
    mx1 = fmaxf(mx1, __shfl_xor_sync(0xffffffffu, mx1, 1));
    mx1 = fmaxf(mx1, __shfl_xor_sync(0xffffffffu, mx1, 2));
    float sum0 = 0.0f, sum1 = 0.0f;
    #pragma unroll
    for (int j = 0; j < 8; j++) {
        sc[j][0] = __expf(sc[j][0] - mx0);
        sc[j][1] = __expf(sc[j][1] - mx0);
        sc[j][2] = __expf(sc[j][2] - mx1);
        sc[j][3] = __expf(sc[j][3] - mx1);
        sum0 += sc[j][0] + sc[j][1];
        sum1 += sc[j][2] + sc[j][3];
    }
    sum0 += __shfl_xor_sync(0xffffffffu, sum0, 1);
    sum0 += __shfl_xor_sync(0xffffffffu, sum0, 2);
    sum1 += __shfl_xor_sync(0xffffffffu, sum1, 1);
    sum1 += __shfl_xor_sync(0xffffffffu, sum1, 2);

    // ---- pack P (unnormalized) as fp16 A fragments ----
    uint32_t pa[4][4];
    #pragma unroll
    for (int kt = 0; kt < 4; kt++) {
        __half2 t;
        t = __float22half2_rn(make_float2(sc[2*kt][0],   sc[2*kt][1]));   pa[kt][0] = *(uint32_t*)&t;
        t = __float22half2_rn(make_float2(sc[2*kt][2],   sc[2*kt][3]));   pa[kt][1] = *(uint32_t*)&t;
        t = __float22half2_rn(make_float2(sc[2*kt+1][0], sc[2*kt+1][1])); pa[kt][2] = *(uint32_t*)&t;
        t = __float22half2_rn(make_float2(sc[2*kt+1][2], sc[2*kt+1][3])); pa[kt][3] = *(uint32_t*)&t;
    }

    // ---- PV ----
    float oacc[8][4];
    #pragma unroll
    for (int nb = 0; nb < 8; nb++)
        #pragma unroll
        for (int p = 0; p < 4; p++) oacc[nb][p] = 0.0f;

    #pragma unroll
    for (int kt = 0; kt < 4; kt++) {
        uint32_t bv[4][4];
        #pragma unroll
        for (int ii = 0; ii < 4; ii++) {
            int rowk  = kt * 16 + ((lane >> 3) & 1) * 8 + (lane & 7);
            int chunk = 2 * ii + (lane >> 4);
            ldm4t(bv[ii], sb + T_VH + (uint32_t)(rowk * 128 + ((chunk ^ (rowk & 7)) << 4)));
        }
        #pragma unroll
        for (int nb = 0; nb < 8; nb++)
            mma16816(oacc[nb], pa[kt], &bv[nb >> 1][(nb & 1) * 2]);
    }

    // ---- normalize + scatter to (b,n,c), fp16 ----
    const float inv0 = 1.0f / sum0;
    const float inv1 = 1.0f / sum1;
    const int g = bg & 63;
    const int b = bg >> 6;
    const int s0 = w * 16 + (lane >> 2);
    const int s1 = s0 + 8;
    const int colb = 2 * (lane & 3);

    #pragma unroll
    for (int hf = 0; hf < 2; hf++) {
        int s = hf ? s1 : s0;
        if (s >= S_) continue;
        float inv = hf ? inv1 : inv0;
        int sy = s / 7, sx = s - sy * 7;
        int n  = ((g >> 3) * 7 + sy) * 56 + (g & 7) * 7 + sx;
        size_t off = ((size_t)(b * NTOK + n)) * C_ + h * 64;
        #pragma unroll
        for (int nb = 0; nb < 8; nb++) {
            __half2 hv;
            hv.x = __float2half_rn(oacc[nb][hf * 2]     * inv);
            hv.y = __float2half_rn(oacc[nb][hf * 2 + 1] * inv);
            *(uint32_t*)(g_ah + off + nb * 8 + colb) = *(uint32_t*)&hv;
        }
    }
}

// ---------------- launch ----------------
extern "C" void kernel_launch(void* const* d_in, const int* in_sizes, int n_in,
                              void* d_out, int out_size)
{
    const float* x      = (const float*)d_in[0];
    const float* w_qkv  = (const float*)d_in[1];
    const float* w_proj = (const float*)d_in[2];
    const float* b_proj = (const float*)d_in[3];
    float* out = (float*)d_out;

    void *qkvp, *xhp, *whp, *php, *ahp;
    cudaGetSymbolAddress(&qkvp, g_qkv);
    cudaGetSymbolAddress(&xhp, g_xh);
    cudaGetSymbolAddress(&whp, g_wh);
    cudaGetSymbolAddress(&php, g_ph);
    cudaGetSymbolAddress(&ahp, g_ah);

    cudaFuncSetAttribute(mma_gemm<QKVN, false, true, true>,
                         cudaFuncAttributeMaxDynamicSharedMemorySize, DYN_SMEM);
    cudaFuncSetAttribute(mma_gemm<C_, true, false, false>,
                         cudaFuncAttributeMaxDynamicSharedMemorySize, DYN_SMEM);

    // 0) conversions
    conv_x_kernel<<<M_ * 128 / 256, 256>>>(x);
    conv_w_kernel<<<QKVN * C_ / 4 / 256, 256>>>(w_qkv, (__half*)whp);
    conv_w_kernel<<<C_ * C_ / 4 / 256, 256>>>(w_proj, (__half*)php);

    // 1) QKV GEMM (fp16 HMMA), fused RoPE, fp16 output
    dim3 g1(QKVN / 128, M_ / 128);
    mma_gemm<QKVN, false, true, true><<<g1, 256, DYN_SMEM>>>(
        (const __half*)xhp, (const __half*)whp, nullptr, qkvp);

    // 2) tensor-core windowed attention (2 heads per block)
    attn_tc_kernel<<<B_ * G_ * NH / 2, 256>>>();

    // 3) projection GEMM + bias (fp16 HMMA, fp32 out)
    dim3 g2(C_ / 128, M_ / 128);
    mma_gemm<C_, true, false, false><<<g2, 256, DYN_SMEM>>>(
        (const __half*)ahp, (const __half*)php, b_proj, out);
}

// round 14
// speedup vs baseline: 1.0636x; 1.0636x over previous
#include <cuda_runtime.h>
#include <cuda_fp16.h>
#include <cstdint>
#include <cstddef>

// ---------------- problem constants ----------------
#define B_    32
#define NTOK  3136
#define C_    512
#define NH    8
#define S_    49
#define G_    64
#define M_    (B_*G_*S_)    // 100352 (784*128)
#define QKVN  1536
#define SCALE_ 0.125f
#define L2T_OVER16 0.8304820237218406f

// ---------------- scratch ----------------
__device__ __half g_qkv[(size_t)M_ * QKVN];      // fp16 qkv (roped), (b,g,s) rows
__device__ __half g_xh[(size_t)M_ * C_];         // gathered x, fp16
__device__ __half g_wh[QKVN * C_];               // w_qkv, fp16
__device__ __half g_ph[C_ * C_];                 // w_proj, fp16
__device__ __half g_ah[(size_t)M_ * C_];         // attention out, fp16, (b,n) rows

// row r (in b,g,s order) -> x row offset (b,n)
__device__ __forceinline__ size_t gather_row_off(int r) {
    int b   = r / (G_ * S_);
    int rem = r - b * (G_ * S_);
    int g   = rem / S_;
    int s   = rem - g * S_;
    int sy  = s / 7;
    int sx  = s - sy * 7;
    int n   = ((g >> 3) * 7 + sy) * 56 + (g & 7) * 7 + sx;
    return ((size_t)b * NTOK + n) * C_;
}

// ---------------- asm wrappers ----------------
__device__ __forceinline__ uint32_t smem_u32(const void* p) {
    uint32_t a;
    asm("{ .reg .u64 t; cvta.to.shared.u64 t, %1; cvt.u32.u64 %0, t; }" : "=r"(a) : "l"(p));
    return a;
}
__device__ __forceinline__ void cp16(uint32_t saddr, const void* g) {
    asm volatile("cp.async.cg.shared.global [%0], [%1], 16;" :: "r"(saddr), "l"(g));
}
__device__ __forceinline__ void cp_commit() {
    asm volatile("cp.async.commit_group;" ::: "memory");
}
__device__ __forceinline__ void cp_wait0() {
    asm volatile("cp.async.wait_group 0;" ::: "memory");
}
__device__ __forceinline__ void cp_wait1() {
    asm volatile("cp.async.wait_group 1;" ::: "memory");
}
__device__ __forceinline__ void cp_wait2() {
    asm volatile("cp.async.wait_group 2;" ::: "memory");
}
__device__ __forceinline__ void cp_wait3() {
    asm volatile("cp.async.wait_group 3;" ::: "memory");
}
__device__ __forceinline__ void cp_wait4() {
    asm volatile("cp.async.wait_group 4;" ::: "memory");
}
__device__ __forceinline__ void ldm4(uint32_t* r, uint32_t addr) {
    asm volatile("ldmatrix.sync.aligned.m8n8.x4.shared.b16 {%0,%1,%2,%3}, [%4];"
        : "=r"(r[0]), "=r"(r[1]), "=r"(r[2]), "=r"(r[3]) : "r"(addr));
}
__device__ __forceinline__ void ldm4t(uint32_t* r, uint32_t addr) {
    asm volatile("ldmatrix.sync.aligned.m8n8.x4.trans.shared.b16 {%0,%1,%2,%3}, [%4];"
        : "=r"(r[0]), "=r"(r[1]), "=r"(r[2]), "=r"(r[3]) : "r"(addr));
}
__device__ __forceinline__ void mma16816(float* c, const uint32_t* a, const uint32_t* b) {
    asm volatile("mma.sync.aligned.m16n8k16.row.col.f32.f16.f16.f32 "
        "{%0,%1,%2,%3}, {%4,%5,%6,%7}, {%8,%9}, {%0,%1,%2,%3};"
        : "+f"(c[0]), "+f"(c[1]), "+f"(c[2]), "+f"(c[3])
        : "r"(a[0]), "r"(a[1]), "r"(a[2]), "r"(a[3]), "r"(b[0]), "r"(b[1]));
}

// ---------------- conversion kernels ----------------
__global__ __launch_bounds__(256) void conv_x_kernel(const float* __restrict__ x) {
    int idx = blockIdx.x * 256 + threadIdx.x;       // M_*128 threads
    int r = idx >> 7;
    int q = (idx & 127) << 2;
    float4 v = *(const float4*)(x + gather_row_off(r) + q);
    __half2 a, b;
    a.x = __float2half_rn(v.x); a.y = __float2half_rn(v.y);
    b.x = __float2half_rn(v.z); b.y = __float2half_rn(v.w);
    size_t o = (size_t)r * C_ + q;
    *(uint2*)(g_xh + o) = make_uint2(*(uint32_t*)&a, *(uint32_t*)&b);
}

__global__ __launch_bounds__(256) void conv_w_kernel(const float* __restrict__ w,
                                                     __half* __restrict__ h) {
    int idx = blockIdx.x * 256 + threadIdx.x;
    size_t o = (size_t)idx << 2;
    float4 v = *(const float4*)(w + o);
    __half2 a, b;
    a.x = __float2half_rn(v.x); a.y = __float2half_rn(v.y);
    b.x = __float2half_rn(v.z); b.y = __float2half_rn(v.w);
    *(uint2*)(h + o) = make_uint2(*(uint32_t*)&a, *(uint32_t*)&b);
}

// ---------------- fp16 HMMA GEMM ----------------
// C[r][d] = sum_k A[r][k]*B[d][k] (+bias / +rope), K=512
// block 128x128, 8 warps (2x4), warp tile 64x32, BK=32, 6-stage cp.async
// Tiles row-paired: 2 logical rows (64B) per 128B physical row, xor swizzle.
// smem per stage: A(8K) B(8K) = 16KB (hole removed vs R11)
#define STG_BYTES 16384u
#define NSTG 6
#define DYN_SMEM (NSTG * STG_BYTES)

// HALFOUT: write __half output (with fused RoPE); else fp32 (+bias)
template <int NCOLS, bool BIAS, bool ROPE, bool HALFOUT>
__global__ __launch_bounds__(256, 2) void mma_gemm(
    const __half* __restrict__ Am, const __half* __restrict__ Bm,
    const float* __restrict__ bias, void* __restrict__ Cout)
{
    extern __shared__ __align__(1024) char dyn[];
    const uint32_t sbase = smem_u32(dyn);

    const int tid  = threadIdx.x;
    const int lane = tid & 31;
    const int wid  = tid >> 5;
    const int wm   = wid >> 2;
    const int wn   = wid & 3;
    const int bm   = blockIdx.y * 128;
    const int bn   = blockIdx.x * 128;

    // ---- loader (R11 mapping): grp0=A (64 thr), grp1=B (64 thr), grps 2,3 idle ----
    const int grp  = tid >> 6;
    const int prow = tid & 63;
    const __half* gsrc = nullptr;
    if      (grp == 0) gsrc = Am + (size_t)bm * C_;
    else if (grp == 1) gsrc = Bm + (size_t)bn * C_;
    const __half* grow = gsrc ? gsrc + (size_t)(2 * prow) * C_ : nullptr;
    const uint32_t smat = sbase + (uint32_t)grp * 8192u + (uint32_t)prow * 128u;
    const int sx = prow & 7;

    auto load_stage = [&](int st, int kc) {
        if (grow) {
            const char* g0 = (const char*)(grow + kc * 32);
            uint32_t rb = smat + (uint32_t)st * STG_BYTES;
            #pragma unroll
            for (int c = 0; c < 8; c++)
                cp16(rb + (uint32_t)((c ^ sx) << 4), g0 + (c >> 2) * (C_ * 2) + (c & 3) * 16);
        }
    };

    // ---- fragment smem offsets (stage-relative), precomputed per ks ----
    const int a_r  = wm * 64 + (lane & 15);
    const int a_cp = lane >> 4;
    const int b_r0 = wn * 32 + (lane & 7) + ((lane & 16) >> 1);
    const int b_cp = (lane >> 3) & 1;

    uint32_t aoff[2][4], boff[2][2];
    #pragma unroll
    for (int ks = 0; ks < 2; ks++) {
        #pragma unroll
        for (int i = 0; i < 4; i++) {
            int r  = a_r + i * 16;
            int pr = r >> 1;
            int pc = ((r & 1) << 2) + 2 * ks + a_cp;
            aoff[ks][i] = (uint32_t)(pr * 128 + ((pc ^ (pr & 7)) << 4));
        }
        #pragma unroll
        for (int jj = 0; jj < 2; jj++) {
            int r  = b_r0 + jj * 16;
            int pr = r >> 1;
            int pc = ((r & 1) << 2) + 2 * ks + b_cp;
            boff[ks][jj] = 8192u + (uint32_t)(pr * 128 + ((pc ^ (pr & 7)) << 4));
        }
    }

    float acc[4][4][4];
    #pragma unroll
    for (int i = 0; i < 4; i++)
        #pragma unroll
        for (int j = 0; j < 4; j++)
            #pragma unroll
            for (int p = 0; p < 4; p++) acc[i][j][p] = 0.0f;

    load_stage(0, 0); cp_commit();
    load_stage(1, 1); cp_commit();
    load_stage(2, 2); cp_commit();
    load_stage(3, 3); cp_commit();
    load_stage(4, 4); cp_commit();

    uint32_t ah[2][4][4], bf[2][2][4];

    auto load_frags = [&](int buf, uint32_t base, int ks) {
        #pragma unroll
        for (int i = 0; i < 4; i++)
            ldm4(ah[buf][i], base + aoff[ks][i]);
        #pragma unroll
        for (int jj = 0; jj < 2; jj++)
            ldm4(bf[buf][jj], base + boff[ks][jj]);
    };
    auto do_mmas = [&](int buf) {
        #pragma unroll
        for (int i = 0; i < 4; i++)
            #pragma unroll
            for (int j = 0; j < 4; j++)
                mma16816(acc[i][j], ah[buf][i], &bf[buf][j >> 1][(j & 1) * 2]);
    };

    #pragma unroll 1
    for (int kc = 0; kc < 16; kc++) {
        if      (kc <= 11) cp_wait4();
        else if (kc == 12) cp_wait3();
        else if (kc == 13) cp_wait2();
        else if (kc == 14) cp_wait1();
        else               cp_wait0();
        __syncthreads();
        if (kc + 5 < 16) { load_stage((kc + 5) % NSTG, kc + 5); cp_commit(); }

        const uint32_t base = sbase + (uint32_t)(kc % NSTG) * STG_BYTES;
        load_frags(0, base, 0);
        load_frags(1, base, 1);
        do_mmas(0);
        do_mmas(1);
    }

    const int orow = bm + wm * 64 + (lane >> 2);
    const int ocol = bn + wn * 32 + (lane & 3) * 2;
    float bvx[4], bvy[4];
    if (BIAS) {
        #pragma unroll
        for (int j = 0; j < 4; j++) { bvx[j] = bias[ocol + j * 8]; bvy[j] = bias[ocol + j * 8 + 1]; }
    }
    #pragma unroll
    for (int i = 0; i < 4; i++) {
        const int rA = orow + i * 16;
        const int rB = rA + 8;
        int sA = 0, sB = 0;
        if (ROPE) { sA = rA % S_; sB = rB % S_; }
        #pragma unroll
        for (int j = 0; j < 4; j++) {
            const int cc = ocol + j * 8;
            float v0 = acc[i][j][0], v1 = acc[i][j][1];
            float v2 = acc[i][j][2], v3 = acc[i][j][3];
            if (ROPE && cc < 1024) {
                int m = (cc & 63) >> 1;
                float freq = exp2f(-(float)(m >> 1) * L2T_OVER16);
                float pA = (m & 1) ? (float)(sA / 7) : (float)(sA % 7);
                float pB = (m & 1) ? (float)(sB / 7) : (float)(sB % 7);
                float snA, csA, snB, csB;
                sincosf(pA * freq, &snA, &csA);
                sincosf(pB * freq, &snB, &csB);
                float t0 = v0 * csA - v1 * snA, t1 = v0 * snA + v1 * csA;
                float t2 = v2 * csB - v3 * snB, t3 = v2 * snB + v3 * csB;
                v0 = t0; v1 = t1; v2 = t2; v3 = t3;
            }
            if (BIAS) { v0 += bvx[j]; v1 += bvy[j]; v2 += bvx[j]; v3 += bvy[j]; }
            if (HALFOUT) {
                __half* Ch = (__half*)Cout;
                __half2 hA, hB;
                hA.x = __float2half_rn(v0); hA.y = __float2half_rn(v1);
                hB.x = __float2half_rn(v2); hB.y = __float2half_rn(v3);
                *(uint32_t*)(Ch + (size_t)rA * NCOLS + cc) = *(uint32_t*)&hA;
                *(uint32_t*)(Ch + (size_t)rB * NCOLS + cc) = *(uint32_t*)&hB;
            } else {
                float* Cf = (float*)Cout;
                *(float2*)(Cf + (size_t)rA * NCOLS + cc) = make_float2(v0, v1);
                *(float2*)(Cf + (size_t)rB * NCOLS + cc) = make_float2(v2, v3);
            }
        }
    }
}

// ---------------- tensor-core windowed attention (fp16 in) — R11 version ----------------
// one block per (b,g,h), 128 threads / 4 warps; S=49 padded to 64.
// smem tiles (64 rows x 128B, xor swizzle): QH 0, KK 8192, VH 16384
#define T_QH 0u
#define T_KK 8192u
#define T_VH 16384u

__global__ __launch_bounds__(128) void attn_tc_kernel() {
    __shared__ __align__(1024) char sm[24576];
    const uint32_t sb = smem_u32(sm);

    const int tid  = threadIdx.x;
    const int lane = tid & 31;
    const int w    = tid >> 5;
    const int h    = blockIdx.x & 7;
    const int bg   = blockIdx.x >> 3;
    const size_t base = (size_t)bg * S_ * QKVN + h * 64;

    // zero-fill (padding rows must be 0)
    #pragma unroll
    for (int i = tid; i < 24576 / 16; i += 128)
        ((uint4*)sm)[i] = make_uint4(0, 0, 0, 0);
    __syncthreads();

    // fill rows 0..48: straight swizzled 16B copies (already fp16)
    for (int i = tid; i < S_ * 8; i += 128) {
        int s   = i >> 3;
        int seg = i & 7;
        size_t ro = base + (size_t)s * QKVN + seg * 8;
        uint4 q = *(const uint4*)(g_qkv + ro);
        uint4 k = *(const uint4*)(g_qkv + ro + 512);
        uint4 v = *(const uint4*)(g_qkv + ro + 1024);
        uint32_t addr = (uint32_t)(s * 128 + ((seg ^ (s & 7)) << 4));
        *(uint4*)(sm + T_QH + addr) = q;
        *(uint4*)(sm + T_KK + addr) = k;
        *(uint4*)(sm + T_VH + addr) = v;
    }
    __syncthreads();

    // ---- QK^T ----
    const int a_r  = w * 16 + (lane & 15);
    const int a_cp = lane >> 4;
    const int b_r0 = (lane & 7) + ((lane & 16) >> 1);
    const int b_cp = (lane >> 3) & 1;

    float sc[8][4];
    #pragma unroll
    for (int j = 0; j < 8; j++)
        #pragma unroll
        for (int p = 0; p < 4; p++) sc[j][p] = 0.0f;

    #pragma unroll
    for (int ks = 0; ks < 4; ks++) {
        uint32_t aq[4], bk[4][4];
        {
            int ch = 2 * ks + a_cp;
            ldm4(aq, sb + T_QH + (uint32_t)(a_r * 128 + ((ch ^ (a_r & 7)) << 4)));
        }
        #pragma unroll
        for (int jn = 0; jn < 4; jn++) {
            int r  = jn * 16 + b_r0;
            int ch = 2 * ks + b_cp;
            ldm4(bk[jn], sb + T_KK + (uint32_t)(r * 128 + ((ch ^ (r & 7)) << 4)));
        }
        #pragma unroll
        for (int j = 0; j < 8; j++)
            mma16816(sc[j], aq, &bk[j >> 1][(j & 1) * 2]);
    }

    // ---- register softmax ----
    #pragma unroll
    for (int j = 0; j < 8; j++) {
        int t0 = j * 8 + 2 * (lane & 3);
        sc[j][0] = (t0     < S_) ? sc[j][0] * SCALE_ : -1e30f;
        sc[j][1] = (t0 + 1 < S_) ? sc[j][1] * SCALE_ : -1e30f;
        sc[j][2] = (t0     < S_) ? sc[j][2] * SCALE_ : -1e30f;
        sc[j][3] = (t0 + 1 < S_) ? sc[j][3] * SCALE_ : -1e30f;
    }
    float mx0 = -1e30f, mx1 = -1e30f;
    #pragma unroll
    for (int j = 0; j < 8; j++) {
        mx0 = fmaxf(mx0, fmaxf(sc[j][0], sc[j][1]));
        mx1 = fmaxf(mx1, fmaxf(sc[j][2], sc[j][3]));
    }
    mx0 = fmaxf(mx0, __shfl_xor_sync(0xffffffffu, mx0, 1));
    mx0 = fmaxf(mx0, __shfl_xor_sync(0xffffffffu, mx0, 2));
    mx1 = fmaxf(mx1, __shfl_xor_sync(0xffffffffu, mx1, 1));
    mx1 = fmaxf(mx1, __shfl_xor_sync(0xffffffffu, mx1, 2));
    float sum0 = 0.0f, sum1 = 0.0f;
    #pragma unroll
    for (int j = 0; j < 8; j++) {
        sc[j][0] = __expf(sc[j][0] - mx0);
        sc[j][1] = __expf(sc[j][1] - mx0);
        sc[j][2] = __expf(sc[j][2] - mx1);
        sc[j][3] = __expf(sc[j][3] - mx1);
        sum0 += sc[j][0] + sc[j][1];
        sum1 += sc[j][2] + sc[j][3];
    }
    sum0 += __shfl_xor_sync(0xffffffffu, sum0, 1);
    sum0 += __shfl_xor_sync(0xffffffffu, sum0, 2);
    sum1 += __shfl_xor_sync(0xffffffffu, sum1, 1);
    sum1 += __shfl_xor_sync(0xffffffffu, sum1, 2);

    // ---- pack P as fp16 A fragments ----
    uint32_t pa[4][4];
    #pragma unroll
    for (int kt = 0; kt < 4; kt++) {
        __half2 t;
        t = __float22half2_rn(make_float2(sc[2*kt][0],   sc[2*kt][1]));   pa[kt][0] = *(uint32_t*)&t;
        t = __float22half2_rn(make_float2(sc[2*kt][2],   sc[2*kt][3]));   pa[kt][1] = *(uint32_t*)&t;
        t = __float22half2_rn(make_float2(sc[2*kt+1][0], sc[2*kt+1][1])); pa[kt][2] = *(uint32_t*)&t;
        t = __float22half2_rn(make_float2(sc[2*kt+1][2], sc[2*kt+1][3])); pa[kt][3] = *(uint32_t*)&t;
    }

    // ---- PV ----
    float oacc[8][4];
    #pragma unroll
    for (int nb = 0; nb < 8; nb++)
        #pragma unroll
        for (int p = 0; p < 4; p++) oacc[nb][p] = 0.0f;

    #pragma unroll
    for (int kt = 0; kt < 4; kt++) {
        uint32_t bv[4][4];
        #pragma unroll
        for (int ii = 0; ii < 4; ii++) {
            int rowk  = kt * 16 + ((lane >> 3) & 1) * 8 + (lane & 7);
            int chunk = 2 * ii + (lane >> 4);
            ldm4t(bv[ii], sb + T_VH + (uint32_t)(rowk * 128 + ((chunk ^ (rowk & 7)) << 4)));
        }
        #pragma unroll
        for (int nb = 0; nb < 8; nb++)
            mma16816(oacc[nb], pa[kt], &bv[nb >> 1][(nb & 1) * 2]);
    }

    // ---- normalize + scatter ----
    const float inv0 = 1.0f / sum0;
    const float inv1 = 1.0f / sum1;
    const int g = bg & 63;
    const int b = bg >> 6;
    const int s0 = w * 16 + (lane >> 2);
    const int s1 = s0 + 8;
    const int colb = 2 * (lane & 3);

    #pragma unroll
    for (int half = 0; half < 2; half++) {
        int s = half ? s1 : s0;
        if (s >= S_) continue;
        float inv = half ? inv1 : inv0;
        int sy = s / 7, sx = s - sy * 7;
        int n  = ((g >> 3) * 7 + sy) * 56 + (g & 7) * 7 + sx;
        size_t off = ((size_t)(b * NTOK + n)) * C_ + h * 64;
        #pragma unroll
        for (int nb = 0; nb < 8; nb++) {
            __half2 hv;
            hv.x = __float2half_rn(oacc[nb][half * 2]     * inv);
            hv.y = __float2half_rn(oacc[nb][half * 2 + 1] * inv);
            *(uint32_t*)(g_ah + off + nb * 8 + colb) = *(uint32_t*)&hv;
        }
    }
}

// ---------------- launch ----------------
extern "C" void kernel_launch(void* const* d_in, const int* in_sizes, int n_in,
                              void* d_out, int out_size)
{
    const float* x      = (const float*)d_in[0];
    const float* w_qkv  = (const float*)d_in[1];
    const float* w_proj = (const float*)d_in[2];
    const float* b_proj = (const float*)d_in[3];
    float* out = (float*)d_out;

    void *qkvp, *xhp, *whp, *php, *ahp;
    cudaGetSymbolAddress(&qkvp, g_qkv);
    cudaGetSymbolAddress(&xhp, g_xh);
    cudaGetSymbolAddress(&whp, g_wh);
    cudaGetSymbolAddress(&php, g_ph);
    cudaGetSymbolAddress(&ahp, g_ah);

    cudaFuncSetAttribute(mma_gemm<QKVN, false, true, true>,
                         cudaFuncAttributeMaxDynamicSharedMemorySize, DYN_SMEM);
    cudaFuncSetAttribute(mma_gemm<C_, true, false, false>,
                         cudaFuncAttributeMaxDynamicSharedMemorySize, DYN_SMEM);

    // 0) conversions
    conv_x_kernel<<<M_ * 128 / 256, 256>>>(x);
    conv_w_kernel<<<QKVN * C_ / 4 / 256, 256>>>(w_qkv, (__half*)whp);
    conv_w_kernel<<<C_ * C_ / 4 / 256, 256>>>(w_proj, (__half*)php);

    // 1) QKV GEMM (fp16 HMMA), fused RoPE, fp16 output
    dim3 g1(QKVN / 128, M_ / 128);
    mma_gemm<QKVN, false, true, true><<<g1, 256, DYN_SMEM>>>(
        (const __half*)xhp, (const __half*)whp, nullptr, qkvp);

    // 2) tensor-core windowed attention
    attn_tc_kernel<<<B_ * G_ * NH, 128>>>();

    // 3) projection GEMM + bias (fp16 HMMA, fp32 out)
    dim3 g2(C_ / 128, M_ / 128);
    mma_gemm<C_, true, false, false><<<g2, 256, DYN_SMEM>>>(
        (const __half*)ahp, (const __half*)php, b_proj, out);
}

// round 15
// speedup vs baseline: 1.0812x; 1.0165x over previous
#include <cuda_runtime.h>
#include <cuda_fp16.h>
#include <cstdint>
#include <cstddef>

// ---------------- problem constants ----------------
#define B_    32
#define NTOK  3136
#define C_    512
#define NH    8
#define S_    49
#define G_    64
#define M_    (B_*G_*S_)    // 100352 (784*128)
#define QKVN  1536
#define SCALE_ 0.125f
#define L2T_OVER16 0.8304820237218406f

// ---------------- scratch ----------------
__device__ __half g_qkv[(size_t)M_ * QKVN];      // fp16 qkv (roped), (b,g,s) rows
__device__ __half g_xh[(size_t)M_ * C_];         // gathered x, fp16
__device__ __half g_wh[QKVN * C_];               // w_qkv, fp16
__device__ __half g_ph[C_ * C_];                 // w_proj, fp16
__device__ __half g_ah[(size_t)M_ * C_];         // attention out, fp16, (b,n) rows

// row r (in b,g,s order) -> x row offset (b,n)
__device__ __forceinline__ size_t gather_row_off(int r) {
    int b   = r / (G_ * S_);
    int rem = r - b * (G_ * S_);
    int g   = rem / S_;
    int s   = rem - g * S_;
    int sy  = s / 7;
    int sx  = s - sy * 7;
    int n   = ((g >> 3) * 7 + sy) * 56 + (g & 7) * 7 + sx;
    return ((size_t)b * NTOK + n) * C_;
}

// ---------------- asm wrappers ----------------
__device__ __forceinline__ uint32_t smem_u32(const void* p) {
    uint32_t a;
    asm("{ .reg .u64 t; cvta.to.shared.u64 t, %1; cvt.u32.u64 %0, t; }" : "=r"(a) : "l"(p));
    return a;
}
__device__ __forceinline__ void cp16(uint32_t saddr, const void* g) {
    asm volatile("cp.async.cg.shared.global [%0], [%1], 16;" :: "r"(saddr), "l"(g));
}
__device__ __forceinline__ void cp_commit() {
    asm volatile("cp.async.commit_group;" ::: "memory");
}
__device__ __forceinline__ void cp_wait0() {
    asm volatile("cp.async.wait_group 0;" ::: "memory");
}
__device__ __forceinline__ void cp_wait1() {
    asm volatile("cp.async.wait_group 1;" ::: "memory");
}
__device__ __forceinline__ void cp_wait2() {
    asm volatile("cp.async.wait_group 2;" ::: "memory");
}
__device__ __forceinline__ void ldm4(uint32_t* r, uint32_t addr) {
    asm volatile("ldmatrix.sync.aligned.m8n8.x4.shared.b16 {%0,%1,%2,%3}, [%4];"
        : "=r"(r[0]), "=r"(r[1]), "=r"(r[2]), "=r"(r[3]) : "r"(addr));
}
__device__ __forceinline__ void ldm4t(uint32_t* r, uint32_t addr) {
    asm volatile("ldmatrix.sync.aligned.m8n8.x4.trans.shared.b16 {%0,%1,%2,%3}, [%4];"
        : "=r"(r[0]), "=r"(r[1]), "=r"(r[2]), "=r"(r[3]) : "r"(addr));
}
__device__ __forceinline__ void mma16816(float* c, const uint32_t* a, const uint32_t* b) {
    asm volatile("mma.sync.aligned.m16n8k16.row.col.f32.f16.f16.f32 "
        "{%0,%1,%2,%3}, {%4,%5,%6,%7}, {%8,%9}, {%0,%1,%2,%3};"
        : "+f"(c[0]), "+f"(c[1]), "+f"(c[2]), "+f"(c[3])
        : "r"(a[0]), "r"(a[1]), "r"(a[2]), "r"(a[3]), "r"(b[0]), "r"(b[1]));
}

// ---------------- merged conversion kernel ----------------
// blocks [0, XB): gathered x -> g_xh
// blocks [XB, XB+WB): w_qkv -> g_wh
// blocks [XB+WB, XB+WB+PB): w_proj -> g_ph
#define XB (M_ * 128 / 256)
#define WB (QKVN * C_ / 4 / 256)
#define PB (C_ * C_ / 4 / 256)

__global__ __launch_bounds__(256) void conv_all_kernel(
    const float* __restrict__ x, const float* __restrict__ w_qkv,
    const float* __restrict__ w_proj)
{
    int bidx = blockIdx.x;
    if (bidx < XB) {
        int idx = bidx * 256 + threadIdx.x;
        int r = idx >> 7;
        int q = (idx & 127) << 2;
        float4 v = *(const float4*)(x + gather_row_off(r) + q);
        __half2 a, b;
        a.x = __float2half_rn(v.x); a.y = __float2half_rn(v.y);
        b.x = __float2half_rn(v.z); b.y = __float2half_rn(v.w);
        size_t o = (size_t)r * C_ + q;
        *(uint2*)(g_xh + o) = make_uint2(*(uint32_t*)&a, *(uint32_t*)&b);
    } else {
        const float* src;
        __half* dst;
        int lb;
        if (bidx < XB + WB) { src = w_qkv;  dst = g_wh; lb = bidx - XB; }
        else                { src = w_proj; dst = g_ph; lb = bidx - XB - WB; }
        int idx = lb * 256 + threadIdx.x;
        size_t o = (size_t)idx << 2;
        float4 v = *(const float4*)(src + o);
        __half2 a, b;
        a.x = __float2half_rn(v.x); a.y = __float2half_rn(v.y);
        b.x = __float2half_rn(v.z); b.y = __float2half_rn(v.w);
        *(uint2*)(dst + o) = make_uint2(*(uint32_t*)&a, *(uint32_t*)&b);
    }
}

// ---------------- fp16 HMMA GEMM (exact R11 structure) ----------------
// C[r][d] = sum_k A[r][k]*B[d][k] (+bias / +rope), K=512
// block 128x128, 8 warps (2x4), warp tile 64x32, BK=32, 4-stage cp.async
// Tiles row-paired: 2 logical rows (64B) per 128B physical row, xor swizzle.
// smem per stage: A(8K) pad(8K) B(8K)
#define STG_BYTES 24576u
#define NSTG 4
#define DYN_SMEM (NSTG * STG_BYTES)

// HALFOUT: write __half output (with fused RoPE); else fp32 (+bias)
template <int NCOLS, bool BIAS, bool ROPE, bool HALFOUT>
__global__ __launch_bounds__(256, 2) void mma_gemm(
    const __half* __restrict__ Am, const __half* __restrict__ Bm,
    const float* __restrict__ bias, void* __restrict__ Cout)
{
    extern __shared__ __align__(1024) char dyn[];
    const uint32_t sbase = smem_u32(dyn);

    const int tid  = threadIdx.x;
    const int lane = tid & 31;
    const int wid  = tid >> 5;
    const int wm   = wid >> 2;
    const int wn   = wid & 3;
    const int bm   = blockIdx.y * 128;
    const int bn   = blockIdx.x * 128;

    const int grp  = tid >> 6;          // 0:A 2:B, others idle
    const int prow = tid & 63;
    const __half* gsrc = nullptr;
    if      (grp == 0) gsrc = Am + (size_t)bm * C_;
    else if (grp == 2) gsrc = Bm + (size_t)bn * C_;
    const __half* grow = gsrc ? gsrc + (size_t)(2 * prow) * C_ : nullptr;
    const uint32_t smat = sbase + (uint32_t)grp * 8192u + (uint32_t)prow * 128u;
    const int sx = prow & 7;

    auto load_stage = [&](int st, int kc) {
        if (grow) {
            const char* g0 = (const char*)(grow + kc * 32);
            uint32_t rb = smat + (uint32_t)st * STG_BYTES;
            #pragma unroll
            for (int c = 0; c < 8; c++)
                cp16(rb + (uint32_t)((c ^ sx) << 4), g0 + (c >> 2) * (C_ * 2) + (c & 3) * 16);
        }
    };

    const int a_r  = wm * 64 + (lane & 15);
    const int a_cp = lane >> 4;
    const int b_r0 = wn * 32 + (lane & 7) + ((lane & 16) >> 1);
    const int b_cp = (lane >> 3) & 1;

    uint32_t aoff[2][4], boff[2][2];
    #pragma unroll
    for (int ks = 0; ks < 2; ks++) {
        #pragma unroll
        for (int i = 0; i < 4; i++) {
            int r  = a_r + i * 16;
            int pr = r >> 1;
            int pc = ((r & 1) << 2) + 2 * ks + a_cp;
            aoff[ks][i] = (uint32_t)(pr * 128 + ((pc ^ (pr & 7)) << 4));
        }
        #pragma unroll
        for (int jj = 0; jj < 2; jj++) {
            int r  = b_r0 + jj * 16;
            int pr = r >> 1;
            int pc = ((r & 1) << 2) + 2 * ks + b_cp;
            boff[ks][jj] = 16384u + (uint32_t)(pr * 128 + ((pc ^ (pr & 7)) << 4));
        }
    }

    float acc[4][4][4];
    #pragma unroll
    for (int i = 0; i < 4; i++)
        #pragma unroll
        for (int j = 0; j < 4; j++)
            #pragma unroll
            for (int p = 0; p < 4; p++) acc[i][j][p] = 0.0f;

    load_stage(0, 0); cp_commit();
    load_stage(1, 1); cp_commit();
    load_stage(2, 2); cp_commit();

    uint32_t ah[2][4][4], bf[2][2][4];

    auto load_frags = [&](int buf, uint32_t base, int ks) {
        #pragma unroll
        for (int i = 0; i < 4; i++)
            ldm4(ah[buf][i], base + aoff[ks][i]);
        #pragma unroll
        for (int jj = 0; jj < 2; jj++)
            ldm4(bf[buf][jj], base + boff[ks][jj]);
    };
    auto do_mmas = [&](int buf) {
        #pragma unroll
        for (int i = 0; i < 4; i++)
            #pragma unroll
            for (int j = 0; j < 4; j++)
                mma16816(acc[i][j], ah[buf][i], &bf[buf][j >> 1][(j & 1) * 2]);
    };

    #pragma unroll 1
    for (int kc = 0; kc < 16; kc++) {
        if      (kc <= 13) cp_wait2();
        else if (kc == 14) cp_wait1();
        else               cp_wait0();
        __syncthreads();
        if (kc + 3 < 16) { load_stage((kc + 3) % NSTG, kc + 3); cp_commit(); }

        const uint32_t base = sbase + (uint32_t)(kc % NSTG) * STG_BYTES;
        load_frags(0, base, 0);
        load_frags(1, base, 1);
        do_mmas(0);
        do_mmas(1);
    }

    const int orow = bm + wm * 64 + (lane >> 2);
    const int ocol = bn + wn * 32 + (lane & 3) * 2;
    float bvx[4], bvy[4];
    if (BIAS) {
        #pragma unroll
        for (int j = 0; j < 4; j++) { bvx[j] = bias[ocol + j * 8]; bvy[j] = bias[ocol + j * 8 + 1]; }
    }
    #pragma unroll
    for (int i = 0; i < 4; i++) {
        const int rA = orow + i * 16;
        const int rB = rA + 8;
        int sA = 0, sB = 0;
        if (ROPE) { sA = rA % S_; sB = rB % S_; }
        #pragma unroll
        for (int j = 0; j < 4; j++) {
            const int cc = ocol + j * 8;
            float v0 = acc[i][j][0], v1 = acc[i][j][1];
            float v2 = acc[i][j][2], v3 = acc[i][j][3];
            if (ROPE && cc < 1024) {
                int m = (cc & 63) >> 1;
                float freq = exp2f(-(float)(m >> 1) * L2T_OVER16);
                float pA = (m & 1) ? (float)(sA / 7) : (float)(sA % 7);
                float pB = (m & 1) ? (float)(sB / 7) : (float)(sB % 7);
                float snA, csA, snB, csB;
                sincosf(pA * freq, &snA, &csA);
                sincosf(pB * freq, &snB, &csB);
                float t0 = v0 * csA - v1 * snA, t1 = v0 * snA + v1 * csA;
                float t2 = v2 * csB - v3 * snB, t3 = v2 * snB + v3 * csB;
                v0 = t0; v1 = t1; v2 = t2; v3 = t3;
            }
            if (BIAS) { v0 += bvx[j]; v1 += bvy[j]; v2 += bvx[j]; v3 += bvy[j]; }
            if (HALFOUT) {
                __half* Ch = (__half*)Cout;
                __half2 hA, hB;
                hA.x = __float2half_rn(v0); hA.y = __float2half_rn(v1);
                hB.x = __float2half_rn(v2); hB.y = __float2half_rn(v3);
                *(uint32_t*)(Ch + (size_t)rA * NCOLS + cc) = *(uint32_t*)&hA;
                *(uint32_t*)(Ch + (size_t)rB * NCOLS + cc) = *(uint32_t*)&hB;
            } else {
                float* Cf = (float*)Cout;
                *(float2*)(Cf + (size_t)rA * NCOLS + cc) = make_float2(v0, v1);
                *(float2*)(Cf + (size_t)rB * NCOLS + cc) = make_float2(v2, v3);
            }
        }
    }
}

// ---------------- tensor-core windowed attention (fp16 in) ----------------
// one block per (b,g,h), 128 threads / 4 warps; S=49 padded to 64.
// smem tiles (64 rows x 128B, xor swizzle): QH 0, KK 8192, VH 16384
// Zero-fill trimmed: only pad rows 49..63 are cleared (disjoint from fill
// rows 0..48, so a single __syncthreads suffices before compute).
#define T_QH 0u
#define T_KK 8192u
#define T_VH 16384u

__global__ __launch_bounds__(128) void attn_tc_kernel() {
    __shared__ __align__(1024) char sm[24576];
    const uint32_t sb = smem_u32(sm);

    const int tid  = threadIdx.x;
    const int lane = tid & 31;
    const int w    = tid >> 5;
    const int h    = blockIdx.x & 7;
    const int bg   = blockIdx.x >> 3;
    const size_t base = (size_t)bg * S_ * QKVN + h * 64;

    // zero only padding rows 49..63 of each tile: 3 tiles x 15 rows x 8 chunks
    for (int i = tid; i < 3 * 15 * 8; i += 128) {
        int tile = i / 120;
        int rem  = i - tile * 120;
        int s    = 49 + (rem >> 3);
        int seg  = rem & 7;
        uint32_t addr = (uint32_t)(tile * 8192 + s * 128 + ((seg ^ (s & 7)) << 4));
        *(uint4*)(sm + addr) = make_uint4(0, 0, 0, 0);
    }

    // fill rows 0..48: straight swizzled 16B copies (already fp16)
    for (int i = tid; i < S_ * 8; i += 128) {
        int s   = i >> 3;
        int seg = i & 7;
        size_t ro = base + (size_t)s * QKVN + seg * 8;
        uint4 q = *(const uint4*)(g_qkv + ro);
        uint4 k = *(const uint4*)(g_qkv + ro + 512);
        uint4 v = *(const uint4*)(g_qkv + ro + 1024);
        uint32_t addr = (uint32_t)(s * 128 + ((seg ^ (s & 7)) << 4));
        *(uint4*)(sm + T_QH + addr) = q;
        *(uint4*)(sm + T_KK + addr) = k;
        *(uint4*)(sm + T_VH + addr) = v;
    }
    __syncthreads();

    // ---- QK^T ----
    const int a_r  = w * 16 + (lane & 15);
    const int a_cp = lane >> 4;
    const int b_r0 = (lane & 7) + ((lane & 16) >> 1);
    const int b_cp = (lane >> 3) & 1;

    float sc[8][4];
    #pragma unroll
    for (int j = 0; j < 8; j++)
        #pragma unroll
        for (int p = 0; p < 4; p++) sc[j][p] = 0.0f;

    #pragma unroll
    for (int ks = 0; ks < 4; ks++) {
        uint32_t aq[4], bk[4][4];
        {
            int ch = 2 * ks + a_cp;
            ldm4(aq, sb + T_QH + (uint32_t)(a_r * 128 + ((ch ^ (a_r & 7)) << 4)));
        }
        #pragma unroll
        for (int jn = 0; jn < 4; jn++) {
            int r  = jn * 16 + b_r0;
            int ch = 2 * ks + b_cp;
            ldm4(bk[jn], sb + T_KK + (uint32_t)(r * 128 + ((ch ^ (r & 7)) << 4)));
        }
        #pragma unroll
        for (int j = 0; j < 8; j++)
            mma16816(sc[j], aq, &bk[j >> 1][(j & 1) * 2]);
    }

    // ---- register softmax ----
    #pragma unroll
    for (int j = 0; j < 8; j++) {
        int t0 = j * 8 + 2 * (lane & 3);
        sc[j][0] = (t0     < S_) ? sc[j][0] * SCALE_ : -1e30f;
        sc[j][1] = (t0 + 1 < S_) ? sc[j][1] * SCALE_ : -1e30f;
        sc[j][2] = (t0     < S_) ? sc[j][2] * SCALE_ : -1e30f;
        sc[j][3] = (t0 + 1 < S_) ? sc[j][3] * SCALE_ : -1e30f;
    }
    float mx0 = -1e30f, mx1 = -1e30f;
    #pragma unroll
    for (int j = 0; j < 8; j++) {
        mx0 = fmaxf(mx0, fmaxf(sc[j][0], sc[j][1]));
        mx1 = fmaxf(mx1, fmaxf(sc[j][2], sc[j][3]));
    }
    mx0 = fmaxf(mx0, __shfl_xor_sync(0xffffffffu, mx0, 1));
    mx0 = fmaxf(mx0, __shfl_xor_sync(0xffffffffu, mx0, 2));
    mx1 = fmaxf(mx1, __shfl_xor_sync(0xffffffffu, mx1, 1));
    mx1 = fmaxf(mx1, __shfl_xor_sync(0xffffffffu, mx1, 2));
    float sum0 = 0.0f, sum1 = 0.0f;
    #pragma unroll
    for (int j = 0; j < 8; j++) {
        sc[j][0] = __expf(sc[j][0] - mx0);
        sc[j][1] = __expf(sc[j][1] - mx0);
        sc[j][2] = __expf(sc[j][2] - mx1);
        sc[j][3] = __expf(sc[j][3] - mx1);
        sum0 += sc[j][0] + sc[j][1];
        sum1 += sc[j][2] + sc[j][3];
    }
    sum0 += __shfl_xor_sync(0xffffffffu, sum0, 1);
    sum0 += __shfl_xor_sync(0xffffffffu, sum0, 2);
    sum1 += __shfl_xor_sync(0xffffffffu, sum1, 1);
    sum1 += __shfl_xor_sync(0xffffffffu, sum1, 2);

    // ---- pack P as fp16 A fragments ----
    uint32_t pa[4][4];
    #pragma unroll
    for (int kt = 0; kt < 4; kt++) {
        __half2 t;
        t = __float22half2_rn(make_float2(sc[2*kt][0],   sc[2*kt][1]));   pa[kt][0] = *(uint32_t*)&t;
        t = __float22half2_rn(make_float2(sc[2*kt][2],   sc[2*kt][3]));   pa[kt][1] = *(uint32_t*)&t;
        t = __float22half2_rn(make_float2(sc[2*kt+1][0], sc[2*kt+1][1])); pa[kt][2] = *(uint32_t*)&t;
        t = __float22half2_rn(make_float2(sc[2*kt+1][2], sc[2*kt+1][3])); pa[kt][3] = *(uint32_t*)&t;
    }

    // ---- PV ----
    float oacc[8][4];
    #pragma unroll
    for (int nb = 0; nb < 8; nb++)
        #pragma unroll
        for (int p = 0; p < 4; p++) oacc[nb][p] = 0.0f;

    #pragma unroll
    for (int kt = 0; kt < 4; kt++) {
        uint32_t bv[4][4];
        #pragma unroll
        for (int ii = 0; ii < 4; ii++) {
            int rowk  = kt * 16 + ((lane >> 3) & 1) * 8 + (lane & 7);
            int chunk = 2 * ii + (lane >> 4);
            ldm4t(bv[ii], sb + T_VH + (uint32_t)(rowk * 128 + ((chunk ^ (rowk & 7)) << 4)));
        }
        #pragma unroll
        for (int nb = 0; nb < 8; nb++)
            mma16816(oacc[nb], pa[kt], &bv[nb >> 1][(nb & 1) * 2]);
    }

    // ---- normalize + scatter ----
    const float inv0 = 1.0f / sum0;
    const float inv1 = 1.0f / sum1;
    const int g = bg & 63;
    const int b = bg >> 6;
    const int s0 = w * 16 + (lane >> 2);
    const int s1 = s0 + 8;
    const int colb = 2 * (lane & 3);

    #pragma unroll
    for (int half = 0; half < 2; half++) {
        int s = half ? s1 : s0;
        if (s >= S_) continue;
        float inv = half ? inv1 : inv0;
        int sy = s / 7, sx = s - sy * 7;
        int n  = ((g >> 3) * 7 + sy) * 56 + (g & 7) * 7 + sx;
        size_t off = ((size_t)(b * NTOK + n)) * C_ + h * 64;
        #pragma unroll
        for (int nb = 0; nb < 8; nb++) {
            __half2 hv;
            hv.x = __float2half_rn(oacc[nb][half * 2]     * inv);
            hv.y = __float2half_rn(oacc[nb][half * 2 + 1] * inv);
            *(uint32_t*)(g_ah + off + nb * 8 + colb) = *(uint32_t*)&hv;
        }
    }
}

// ---------------- launch ----------------
extern "C" void kernel_launch(void* const* d_in, const int* in_sizes, int n_in,
                              void* d_out, int out_size)
{
    const float* x      = (const float*)d_in[0];
    const float* w_qkv  = (const float*)d_in[1];
    const float* w_proj = (const float*)d_in[2];
    const float* b_proj = (const float*)d_in[3];
    float* out = (float*)d_out;

    void *qkvp, *xhp, *whp, *php, *ahp;
    cudaGetSymbolAddress(&qkvp, g_qkv);
    cudaGetSymbolAddress(&xhp, g_xh);
    cudaGetSymbolAddress(&whp, g_wh);
    cudaGetSymbolAddress(&php, g_ph);
    cudaGetSymbolAddress(&ahp, g_ah);

    cudaFuncSetAttribute(mma_gemm<QKVN, false, true, true>,
                         cudaFuncAttributeMaxDynamicSharedMemorySize, DYN_SMEM);
    cudaFuncSetAttribute(mma_gemm<C_, true, false, false>,
                         cudaFuncAttributeMaxDynamicSharedMemorySize, DYN_SMEM);

    // 0) all conversions in one launch
    conv_all_kernel<<<XB + WB + PB, 256>>>(x, w_qkv, w_proj);

    // 1) QKV GEMM (fp16 HMMA), fused RoPE, fp16 output
    dim3 g1(QKVN / 128, M_ / 128);
    mma_gemm<QKVN, false, true, true><<<g1, 256, DYN_SMEM>>>(
        (const __half*)xhp, (const __half*)whp, nullptr, qkvp);

    // 2) tensor-core windowed attention
    attn_tc_kernel<<<B_ * G_ * NH, 128>>>();

    // 3) projection GEMM + bias (fp16 HMMA, fp32 out)
    dim3 g2(C_ / 128, M_ / 128);
    mma_gemm<C_, true, false, false><<<g2, 256, DYN_SMEM>>>(
        (const __half*)ahp, (const __half*)php, b_proj, out);
}